// round 4
// baseline (speedup 1.0000x reference)
#include <cuda_runtime.h>

#define S_    512
#define P_    196
#define Q_    48
#define CB_   8
#define R_    32
#define C_    10
#define NMID  6

#define THREADS 512

// shared memory layout (floats)
#define OFF_X   0                      // 9408   x[p][q]
#define OFF_M   9408                   // 12544  M[p][ab]
#define OFF_G   21952                  // 2*8192 G tile double buffer [ab(64)][col(128)]
#define OFF_CK  38336                  // 3072   Ck as [q][a*8+b]
#define OFF_ST  41408                  // 2*2560 state[a*320 + l*10 + c]
#define OFF_OUT 46528                  // 16
#define SMEM_FLOATS 46544

#define FMA16(A0,A1,A2,A3,MV,AV)                                             \
    A0.x += MV.x * AV.x; A0.y += MV.x * AV.y; A0.z += MV.x * AV.z; A0.w += MV.x * AV.w; \
    A1.x += MV.y * AV.x; A1.y += MV.y * AV.y; A1.z += MV.y * AV.z; A1.w += MV.y * AV.w; \
    A2.x += MV.z * AV.x; A2.y += MV.z * AV.y; A2.z += MV.z * AV.z; A2.w += MV.z * AV.w; \
    A3.x += MV.w * AV.x; A3.y += MV.w * AV.y; A3.z += MV.w * AV.z; A3.w += MV.w * AV.w;

__global__ void __launch_bounds__(THREADS, 1)
tctl_kernel(const float* __restrict__ x,
            const float* __restrict__ cf,   // [Q][CB]
            const float* __restrict__ cm,   // [NMID][CB][Q][CB]
            const float* __restrict__ cl,   // [CB][Q]
            const float* __restrict__ tf,   // [C][P][R]
            const float* __restrict__ tm,   // [NMID][R][P][R]
            const float* __restrict__ tl,   // [R][P]
            float* __restrict__ out)        // [S][C]
{
    extern __shared__ float smem[];
    float* sx     = smem + OFF_X;
    float* sM     = smem + OFF_M;
    float* sG     = smem + OFF_G;
    float* sCk    = smem + OFF_CK;
    float* sState = smem + OFF_ST;
    float* sOut   = smem + OFF_OUT;

    const int tid = threadIdx.x;
    const int s   = blockIdx.x;

    // ---------- load x sample ----------
    {
        const float4* xg = (const float4*)(x + (size_t)s * (P_ * Q_));
        float4* sx4 = (float4*)sx;
        for (int i = tid; i < (P_ * Q_) / 4; i += THREADS) sx4[i] = xg[i];
    }
    for (int i = tid; i < Q_ * CB_; i += THREADS) sCk[i] = cf[i];
    __syncthreads();

    // ---------- carriage 1: y1[p,b] = sum_q x[p,q] cf[q,b]  (into sM[p*8+b]) ----------
    for (int e = tid; e < P_ * CB_; e += THREADS) {
        int p = e >> 3, b = e & 7;
        const float* xp = sx + p * Q_;
        float acc = 0.f;
        #pragma unroll
        for (int q = 0; q < Q_; q++) acc += xp[q] * sCk[q * 8 + b];
        sM[e] = acc;
    }
    __syncthreads();

    // state0[b,r,c] = sum_p y1[p,b] * tf[c,p,r]   (threads 0..255: b=t>>5, r=t&31)
    if (tid < 256) {
        const int b = tid >> 5, r = tid & 31;
        float acc[C_];
        #pragma unroll
        for (int c = 0; c < C_; c++) acc[c] = 0.f;
        for (int p = 0; p < P_; p++) {
            float y = sM[p * 8 + b];
            #pragma unroll
            for (int c = 0; c < C_; c++)
                acc[c] += y * tf[((size_t)c * P_ + p) * R_ + r];
        }
        #pragma unroll
        for (int c = 0; c < C_; c++) sState[b * 320 + r * 10 + c] = acc[c];
    }

    // ---------- mid carriages ----------
    const int rowGrp = tid >> 5;        // 0..15 -> G rows ab = rowGrp*4..+3
    const int colGrp = tid & 31;        // 0..31 -> G cols colGrp*4..+3 (of 128)
    const int bU  = tid >> 6;
    const int rU  = (tid >> 1) & 31;
    const int chU = tid & 1;

    for (int k = 0; k < NMID; k++) {
        const float* Ck = cm + (size_t)k * (CB_ * Q_ * CB_);
        const float* Ak = tm + (size_t)k * (R_ * P_ * R_);
        float* stCur = sState + (k & 1) * 2560;
        float* stNxt = sState + ((k & 1) ^ 1) * 2560;

        __syncthreads();  // state writes + last step's sM reads done

        // Ck -> sCk as [q][a*8+b]
        for (int i = tid; i < CB_ * Q_ * CB_; i += THREADS) {
            int a  = i / (Q_ * CB_);
            int qb = i % (Q_ * CB_);
            int q = qb >> 3, b = qb & 7;
            sCk[q * 64 + a * 8 + b] = Ck[i];
        }
        __syncthreads();

        // M[p][ab] = sum_q x[p,q] * Ck[a,q,b]
        for (int e4 = tid; e4 < (P_ * 64) / 4; e4 += THREADS) {
            int p  = e4 >> 4;
            int c4 = e4 & 15;
            const float*  xp  = sx + p * Q_;
            const float4* ck4 = ((const float4*)sCk) + c4;
            float4 acc = make_float4(0.f, 0.f, 0.f, 0.f);
            #pragma unroll
            for (int q = 0; q < Q_; q++) {
                float  f  = xp[q];
                float4 cv = ck4[q * 16];
                acc.x += f * cv.x; acc.y += f * cv.y;
                acc.z += f * cv.z; acc.w += f * cv.w;
            }
            ((float4*)sM)[e4] = acc;
        }
        __syncthreads();  // sM ready for tile reads

        float ns[5];
        #pragma unroll
        for (int c = 0; c < 5; c++) ns[c] = 0.f;

        // 8 tiles over groups of 4 l-values; G tile [64 rows][4*32 cols], double-buffered
        for (int lt = 0; lt < 8; lt++) {
            float* gbuf = sG + (lt & 1) * 8192;

            const int   l   = lt * 4 + (colGrp >> 3);
            const int   r0  = (colGrp & 7) * 4;
            const float* AkL = Ak + (size_t)l * (P_ * R_) + r0;
            const float4* mrow = ((const float4*)sM) + rowGrp;

            float4 a0 = make_float4(0.f,0.f,0.f,0.f);
            float4 a1 = make_float4(0.f,0.f,0.f,0.f);
            float4 a2 = make_float4(0.f,0.f,0.f,0.f);
            float4 a3 = make_float4(0.f,0.f,0.f,0.f);

            // deep-pipelined p loop: av prefetch depth 4 (L2 lat ~260cyc), mv depth 2
            float4 avp[4];
            float4 mvp[2];
            #pragma unroll
            for (int j = 0; j < 4; j++) avp[j] = *(const float4*)(AkL + j * R_);
            mvp[0] = mrow[0];
            mvp[1] = mrow[16];

            #pragma unroll 1
            for (int pb = 0; pb < P_; pb += 4) {
                #pragma unroll
                for (int u = 0; u < 4; u++) {
                    const int p = pb + u;
                    float4 av = avp[u];
                    float4 mv = mvp[u & 1];
                    if (p + 4 < P_) avp[u]     = *(const float4*)(AkL + (p + 4) * R_);
                    if (p + 2 < P_) mvp[u & 1] = mrow[(p + 2) * 16];
                    FMA16(a0, a1, a2, a3, mv, av)
                }
            }

            float4* g4 = (float4*)gbuf;
            g4[(rowGrp * 4 + 0) * 32 + colGrp] = a0;
            g4[(rowGrp * 4 + 1) * 32 + colGrp] = a1;
            g4[(rowGrp * 4 + 2) * 32 + colGrp] = a2;
            g4[(rowGrp * 4 + 3) * 32 + colGrp] = a3;
            __syncthreads();  // gbuf complete (and prev tile's update finished)

            // ns[c] += sum_{a,lj} state[a, lt*4+lj, c] * G[a*8+bU, lj*32+rU]
            #pragma unroll
            for (int a = 0; a < CB_; a++) {
                #pragma unroll
                for (int lj = 0; lj < 4; lj++) {
                    float g = gbuf[(a * 8 + bU) * 128 + lj * 32 + rU];
                    const float* st = stCur + a * 320 + (lt * 4 + lj) * 10 + chU * 5;
                    #pragma unroll
                    for (int c = 0; c < 5; c++) ns[c] += st[c] * g;
                }
            }
        }

        #pragma unroll
        for (int c = 0; c < 5; c++) stNxt[bU * 320 + rU * 10 + chU * 5 + c] = ns[c];
    }

    // ---------- last carriage ----------
    __syncthreads();

    // z[p,a] = sum_q x[p,q] cl[a,q]  (into sM[p*8+a])
    for (int e = tid; e < P_ * CB_; e += THREADS) {
        int p = e >> 3, a = e & 7;
        const float* xp  = sx + p * Q_;
        const float* cla = cl + a * Q_;
        float acc = 0.f;
        #pragma unroll
        for (int q = 0; q < Q_; q++) acc += xp[q] * cla[q];
        sM[e] = acc;
    }
    if (tid < C_) sOut[tid] = 0.f;
    __syncthreads();

    // GN[a,l] = sum_p z[p,a] tl[l,p];  out[c] = sum_{a,l} state[a,l,c]*GN[a,l]
    if (tid < 256) {
        const int a = tid >> 5, l = tid & 31;
        const float* tlr = tl + l * P_;
        float gn = 0.f;
        for (int p = 0; p < P_; p++) gn += sM[p * 8 + a] * tlr[p];

        const float* st = sState + /*final buffer 0 (NMID even)*/ a * 320 + l * 10;
        #pragma unroll
        for (int c = 0; c < C_; c++) atomicAdd(&sOut[c], st[c] * gn);
    }
    __syncthreads();

    if (tid < C_) out[(size_t)s * C_ + tid] = sOut[tid];
}

extern "C" void kernel_launch(void* const* d_in, const int* in_sizes, int n_in,
                              void* d_out, int out_size)
{
    const float* x  = (const float*)d_in[0];
    const float* cf = (const float*)d_in[1];
    const float* cm = (const float*)d_in[2];
    const float* cl = (const float*)d_in[3];
    const float* tf = (const float*)d_in[4];
    const float* tm = (const float*)d_in[5];
    const float* tl = (const float*)d_in[6];
    float* out = (float*)d_out;

    size_t shbytes = SMEM_FLOATS * sizeof(float);
    cudaFuncSetAttribute(tctl_kernel, cudaFuncAttributeMaxDynamicSharedMemorySize,
                         (int)shbytes);
    tctl_kernel<<<S_, THREADS, shbytes>>>(x, cf, cm, cl, tf, tm, tl, out);
}

// round 6
// speedup vs baseline: 1.4211x; 1.4211x over previous
#include <cuda_runtime.h>
#include <cstdint>

#define S_    512
#define P_    196
#define Q_    48
#define CB_   8
#define R_    32
#define C_    10
#define NMID  6

#define THREADS 512

// shared memory layout (floats)
#define OFF_X   0                      // 9408   x[p][q]
#define OFF_M   9408                   // 12544  M[p][ab]
#define OFF_G   21952                  // 16384  G tile [ab(64)][col(256)]  col = l_loc*32 + r
#define OFF_CK  38336                  // 3072   Ck as [q][a*8+b]
#define OFF_ST  41408                  // 2*2560 state[a*320 + l*10 + c]
#define OFF_OUT 46528                  // 16
#define SMEM_FLOATS 46544

// M row stride in ulonglong2 units: 64 floats = 16 ulonglong2
#define MSTRIDE 16

__device__ __forceinline__ void ffma2(uint64_t& d, uint64_t a, uint64_t b) {
    asm("fma.rn.f32x2 %0, %1, %2, %0;" : "+l"(d) : "l"(a), "l"(b));
}
__device__ __forceinline__ uint64_t bcast2(float v) {
    uint64_t r; unsigned u = __float_as_uint(v);
    asm("mov.b64 %0, {%1, %1};" : "=l"(r) : "r"(u));
    return r;
}
__device__ __forceinline__ float2 unpack2(uint64_t v) {
    float2 f;
    asm("mov.b64 {%0, %1}, %2;" : "=f"(f.x), "=f"(f.y) : "l"(v));
    return f;
}

// 16 packed-FMA2 block: acc[k*4+j] (+)= (m pair k) * bcast(av lane j)
#define FFMA2_BLOCK(ACC, MA, MB, AV)                                   \
    {                                                                  \
        uint64_t b0 = bcast2(AV.x), b1 = bcast2(AV.y);                 \
        uint64_t b2 = bcast2(AV.z), b3 = bcast2(AV.w);                 \
        ffma2(ACC[0],  MA.x, b0); ffma2(ACC[1],  MA.x, b1);            \
        ffma2(ACC[2],  MA.x, b2); ffma2(ACC[3],  MA.x, b3);            \
        ffma2(ACC[4],  MA.y, b0); ffma2(ACC[5],  MA.y, b1);            \
        ffma2(ACC[6],  MA.y, b2); ffma2(ACC[7],  MA.y, b3);            \
        ffma2(ACC[8],  MB.x, b0); ffma2(ACC[9],  MB.x, b1);            \
        ffma2(ACC[10], MB.x, b2); ffma2(ACC[11], MB.x, b3);            \
        ffma2(ACC[12], MB.y, b0); ffma2(ACC[13], MB.y, b1);            \
        ffma2(ACC[14], MB.y, b2); ffma2(ACC[15], MB.y, b3);            \
    }

__global__ void __launch_bounds__(THREADS, 1)
tctl_kernel(const float* __restrict__ x,
            const float* __restrict__ cf,   // [Q][CB]
            const float* __restrict__ cm,   // [NMID][CB][Q][CB]
            const float* __restrict__ cl,   // [CB][Q]
            const float* __restrict__ tf,   // [C][P][R]
            const float* __restrict__ tm,   // [NMID][R][P][R]
            const float* __restrict__ tl,   // [R][P]
            float* __restrict__ out)        // [S][C]
{
    extern __shared__ float smem[];
    float* sx     = smem + OFF_X;
    float* sM     = smem + OFF_M;
    float* sG     = smem + OFF_G;
    float* sCk    = smem + OFF_CK;
    float* sState = smem + OFF_ST;
    float* sOut   = smem + OFF_OUT;

    const int tid = threadIdx.x;
    const int s   = blockIdx.x;

    // ---------- load x sample ----------
    {
        const float4* xg = (const float4*)(x + (size_t)s * (P_ * Q_));
        float4* sx4 = (float4*)sx;
        for (int i = tid; i < (P_ * Q_) / 4; i += THREADS) sx4[i] = xg[i];
    }
    for (int i = tid; i < Q_ * CB_; i += THREADS) sCk[i] = cf[i];
    __syncthreads();

    // ---------- carriage 1: y1[p,b] = sum_q x[p,q] cf[q,b] (into sM[p*8+b]) ----------
    for (int e = tid; e < P_ * CB_; e += THREADS) {
        int p = e >> 3, b = e & 7;
        const float* xp = sx + p * Q_;
        float acc = 0.f;
        #pragma unroll
        for (int q = 0; q < Q_; q++) acc += xp[q] * sCk[q * 8 + b];
        sM[e] = acc;
    }
    __syncthreads();

    // state0[b,r,c] = sum_p y1[p,b] * tf[c,p,r]
    if (tid < 256) {
        const int b = tid >> 5, r = tid & 31;
        float acc[C_];
        #pragma unroll
        for (int c = 0; c < C_; c++) acc[c] = 0.f;
        for (int p = 0; p < P_; p++) {
            float y = sM[p * 8 + b];
            #pragma unroll
            for (int c = 0; c < C_; c++)
                acc[c] += y * tf[((size_t)c * P_ + p) * R_ + r];
        }
        #pragma unroll
        for (int c = 0; c < C_; c++) sState[b * 320 + r * 10 + c] = acc[c];
    }

    // ---------- mid carriages ----------
    const int rowGrp = tid >> 6;        // 0..7  -> G rows ab = rowGrp*8..+7
    const int colGrp = tid & 63;        // 0..63 -> G cols colGrp*4..+3 (of 256)
    const int bU  = tid >> 6;
    const int rU  = (tid >> 1) & 31;
    const int chU = tid & 1;

    for (int k = 0; k < NMID; k++) {
        const float* Ck = cm + (size_t)k * (CB_ * Q_ * CB_);
        const float* Ak = tm + (size_t)k * (R_ * P_ * R_);
        float* stCur = sState + (k & 1) * 2560;
        float* stNxt = sState + ((k & 1) ^ 1) * 2560;

        __syncthreads();  // state writes + last step's sM/sG reads done

        // Ck -> sCk as [q][a*8+b]
        for (int i = tid; i < CB_ * Q_ * CB_; i += THREADS) {
            int a  = i / (Q_ * CB_);
            int qb = i % (Q_ * CB_);
            int q = qb >> 3, b = qb & 7;
            sCk[q * 64 + a * 8 + b] = Ck[i];
        }
        __syncthreads();

        // M[p][ab] = sum_q x[p,q] * Ck[a,q,b]
        for (int e4 = tid; e4 < (P_ * 64) / 4; e4 += THREADS) {
            int p  = e4 >> 4;
            int c4 = e4 & 15;
            const float*  xp  = sx + p * Q_;
            const float4* ck4 = ((const float4*)sCk) + c4;
            float4 acc = make_float4(0.f, 0.f, 0.f, 0.f);
            #pragma unroll
            for (int q = 0; q < Q_; q++) {
                float  f  = xp[q];
                float4 cv = ck4[q * 16];
                acc.x += f * cv.x; acc.y += f * cv.y;
                acc.z += f * cv.z; acc.w += f * cv.w;
            }
            ((float4*)sM)[e4] = acc;
        }

        float ns[5];
        #pragma unroll
        for (int c = 0; c < 5; c++) ns[c] = 0.f;

        // 4 tiles over groups of 8 l-values; G tile [64 rows][8*32 cols]
        for (int lt = 0; lt < 4; lt++) {
            __syncthreads();  // sM ready (lt=0) / prev tile's G reads done

            const int   l   = lt * 8 + (colGrp >> 3);
            const int   r0  = (colGrp & 7) * 4;
            const float* AkL = Ak + (size_t)l * (P_ * R_) + r0;
            // this thread's 8 M-rows as packed f32x2 pairs
            const ulonglong2* mbase = ((const ulonglong2*)sM) + rowGrp * 2;

            uint64_t acc[16];
            #pragma unroll
            for (int i = 0; i < 16; i++) acc[i] = 0ull;

            // 2-stage av prefetch, 1-stage m prefetch; peeled tail, no predication
            float4     av0 = *(const float4*)(AkL);
            float4     av1 = *(const float4*)(AkL + R_);
            ulonglong2 ma  = mbase[0];
            ulonglong2 mb  = mbase[1];

            #pragma unroll 1
            for (int p = 0; p < P_ - 2; p += 2) {
                float4     avn0 = *(const float4*)(AkL + (p + 2) * R_);
                ulonglong2 ma1  = mbase[(p + 1) * MSTRIDE];
                ulonglong2 mb1  = mbase[(p + 1) * MSTRIDE + 1];
                FFMA2_BLOCK(acc, ma, mb, av0)
                float4     avn1 = *(const float4*)(AkL + (p + 3) * R_);
                ulonglong2 ma2  = mbase[(p + 2) * MSTRIDE];
                ulonglong2 mb2  = mbase[(p + 2) * MSTRIDE + 1];
                FFMA2_BLOCK(acc, ma1, mb1, av1)
                av0 = avn0; av1 = avn1; ma = ma2; mb = mb2;
            }
            // tail: p = 194, 195
            FFMA2_BLOCK(acc, ma, mb, av0)
            ma = mbase[195 * MSTRIDE];
            mb = mbase[195 * MSTRIDE + 1];
            FFMA2_BLOCK(acc, ma, mb, av1)

            // write 8 rows x 4 cols to G
            float4* g4 = (float4*)sG;
            #pragma unroll
            for (int kk = 0; kk < 4; kk++) {
                float2 l0 = unpack2(acc[kk * 4 + 0]);
                float2 l1 = unpack2(acc[kk * 4 + 1]);
                float2 l2 = unpack2(acc[kk * 4 + 2]);
                float2 l3 = unpack2(acc[kk * 4 + 3]);
                g4[(rowGrp * 8 + kk * 2 + 0) * 64 + colGrp] =
                    make_float4(l0.x, l1.x, l2.x, l3.x);
                g4[(rowGrp * 8 + kk * 2 + 1) * 64 + colGrp] =
                    make_float4(l0.y, l1.y, l2.y, l3.y);
            }
            __syncthreads();  // G tile complete

            // ns[c] += sum_{a,lj} state[a, lt*8+lj, c] * G[a*8+bU, lj*32+rU]
            #pragma unroll
            for (int a = 0; a < CB_; a++) {
                #pragma unroll
                for (int lj = 0; lj < 8; lj++) {
                    float g = sG[(a * 8 + bU) * 256 + lj * 32 + rU];
                    const float* st = stCur + a * 320 + (lt * 8 + lj) * 10 + chU * 5;
                    #pragma unroll
                    for (int c = 0; c < 5; c++) ns[c] += st[c] * g;
                }
            }
        }

        #pragma unroll
        for (int c = 0; c < 5; c++) stNxt[bU * 320 + rU * 10 + chU * 5 + c] = ns[c];
    }

    // ---------- last carriage ----------
    __syncthreads();

    // z[p,a] = sum_q x[p,q] cl[a,q]  (into sM[p*8+a])
    for (int e = tid; e < P_ * CB_; e += THREADS) {
        int p = e >> 3, a = e & 7;
        const float* xp  = sx + p * Q_;
        const float* cla = cl + a * Q_;
        float acc = 0.f;
        #pragma unroll
        for (int q = 0; q < Q_; q++) acc += xp[q] * cla[q];
        sM[e] = acc;
    }
    if (tid < C_) sOut[tid] = 0.f;
    __syncthreads();

    // GN[a,l] = sum_p z[p,a] tl[l,p];  out[c] = sum_{a,l} state[a,l,c]*GN[a,l]
    if (tid < 256) {
        const int a = tid >> 5, l = tid & 31;
        const float* tlr = tl + l * P_;
        float gn = 0.f;
        for (int p = 0; p < P_; p++) gn += sM[p * 8 + a] * tlr[p];

        const float* st = sState + /*final buffer 0 (NMID even)*/ a * 320 + l * 10;
        #pragma unroll
        for (int c = 0; c < C_; c++) atomicAdd(&sOut[c], st[c] * gn);
    }
    __syncthreads();

    if (tid < C_) out[(size_t)s * C_ + tid] = sOut[tid];
}

extern "C" void kernel_launch(void* const* d_in, const int* in_sizes, int n_in,
                              void* d_out, int out_size)
{
    const float* x  = (const float*)d_in[0];
    const float* cf = (const float*)d_in[1];
    const float* cm = (const float*)d_in[2];
    const float* cl = (const float*)d_in[3];
    const float* tf = (const float*)d_in[4];
    const float* tm = (const float*)d_in[5];
    const float* tl = (const float*)d_in[6];
    float* out = (float*)d_out;

    size_t shbytes = SMEM_FLOATS * sizeof(float);
    cudaFuncSetAttribute(tctl_kernel, cudaFuncAttributeMaxDynamicSharedMemorySize,
                         (int)shbytes);
    tctl_kernel<<<S_, THREADS, shbytes>>>(x, cf, cm, cl, tf, tm, tl, out);
}

// round 7
// speedup vs baseline: 1.5370x; 1.0815x over previous
#include <cuda_runtime.h>
#include <cstdint>

#define S_    512
#define P_    196
#define Q_    48
#define CB_   8
#define R_    32
#define C_    10
#define NMID  6

#define THREADS 512

// shared memory layout (floats)
#define OFF_X   0                      // 9408   x[p][q]
#define OFF_M   9408                   // 12544  M[p][ab]
#define OFF_G   21952                  // 16384  G tile [ab(64)][col(256)]  col = l_loc*32 + r
#define OFF_CK  38336                  // 3072   Ck as [q][a*8+b]
#define OFF_ST  41408                  // 2*2560 state[a*320 + l*10 + c]
#define OFF_OUT 46528                  // 16
#define SMEM_FLOATS 46544

// M row stride in ulonglong2 units: 64 floats = 16 ulonglong2
#define MSTRIDE 16

__device__ __forceinline__ void ffma2(uint64_t& d, uint64_t a, uint64_t b) {
    asm("fma.rn.f32x2 %0, %1, %2, %0;" : "+l"(d) : "l"(a), "l"(b));
}
__device__ __forceinline__ uint64_t bcast2(float v) {
    uint64_t r; unsigned u = __float_as_uint(v);
    asm("mov.b64 %0, {%1, %1};" : "=l"(r) : "r"(u));
    return r;
}
__device__ __forceinline__ float2 unpack2(uint64_t v) {
    float2 f;
    asm("mov.b64 {%0, %1}, %2;" : "=f"(f.x), "=f"(f.y) : "l"(v));
    return f;
}

// 16 packed-FMA2 block: acc[k*4+j] (+)= (m pair k) * bcast(av lane j)
#define FFMA2_BLOCK(ACC, MA, MB, AV)                                   \
    {                                                                  \
        uint64_t b0 = bcast2(AV.x), b1 = bcast2(AV.y);                 \
        uint64_t b2 = bcast2(AV.z), b3 = bcast2(AV.w);                 \
        ffma2(ACC[0],  MA.x, b0); ffma2(ACC[1],  MA.x, b1);            \
        ffma2(ACC[2],  MA.x, b2); ffma2(ACC[3],  MA.x, b3);            \
        ffma2(ACC[4],  MA.y, b0); ffma2(ACC[5],  MA.y, b1);            \
        ffma2(ACC[6],  MA.y, b2); ffma2(ACC[7],  MA.y, b3);            \
        ffma2(ACC[8],  MB.x, b0); ffma2(ACC[9],  MB.x, b1);            \
        ffma2(ACC[10], MB.x, b2); ffma2(ACC[11], MB.x, b3);            \
        ffma2(ACC[12], MB.y, b0); ffma2(ACC[13], MB.y, b1);            \
        ffma2(ACC[14], MB.y, b2); ffma2(ACC[15], MB.y, b3);            \
    }

__global__ void __launch_bounds__(THREADS, 1)
tctl_kernel(const float* __restrict__ x,
            const float* __restrict__ cf,   // [Q][CB]
            const float* __restrict__ cm,   // [NMID][CB][Q][CB]
            const float* __restrict__ cl,   // [CB][Q]
            const float* __restrict__ tf,   // [C][P][R]
            const float* __restrict__ tm,   // [NMID][R][P][R]
            const float* __restrict__ tl,   // [R][P]
            float* __restrict__ out)        // [S][C]
{
    extern __shared__ float smem[];
    float* sx     = smem + OFF_X;
    float* sM     = smem + OFF_M;
    float* sG     = smem + OFF_G;
    float* sCk    = smem + OFF_CK;
    float* sState = smem + OFF_ST;
    float* sOut   = smem + OFF_OUT;

    const int tid = threadIdx.x;
    const int s   = blockIdx.x;

    // ---------- load x sample ----------
    {
        const float4* xg = (const float4*)(x + (size_t)s * (P_ * Q_));
        float4* sx4 = (float4*)sx;
        for (int i = tid; i < (P_ * Q_) / 4; i += THREADS) sx4[i] = xg[i];
    }
    for (int i = tid; i < Q_ * CB_; i += THREADS) sCk[i] = cf[i];
    __syncthreads();

    // ---------- carriage 1: y1[p,b] = sum_q x[p,q] cf[q,b] (into sM[p*8+b]) ----------
    for (int e = tid; e < P_ * CB_; e += THREADS) {
        int p = e >> 3, b = e & 7;
        const float* xp = sx + p * Q_;
        float acc = 0.f;
        #pragma unroll
        for (int q = 0; q < Q_; q++) acc += xp[q] * sCk[q * 8 + b];
        sM[e] = acc;
    }
    __syncthreads();

    // state0[b,r,c] = sum_p y1[p,b] * tf[c,p,r]
    if (tid < 256) {
        const int b = tid >> 5, r = tid & 31;
        float acc[C_];
        #pragma unroll
        for (int c = 0; c < C_; c++) acc[c] = 0.f;
        for (int p = 0; p < P_; p++) {
            float y = sM[p * 8 + b];
            #pragma unroll
            for (int c = 0; c < C_; c++)
                acc[c] += y * tf[((size_t)c * P_ + p) * R_ + r];
        }
        #pragma unroll
        for (int c = 0; c < C_; c++) sState[b * 320 + r * 10 + c] = acc[c];
    }

    // ---------- mid carriages ----------
    const int rowGrp = tid >> 6;        // 0..7  -> G rows ab = rowGrp*8..+7
    const int colGrp = tid & 63;        // 0..63 -> G cols colGrp*4..+3 (of 256)
    const int bU  = tid >> 6;
    const int rU  = (tid >> 1) & 31;
    const int chU = tid & 1;

    for (int k = 0; k < NMID; k++) {
        const float* Ck = cm + (size_t)k * (CB_ * Q_ * CB_);
        const float* Ak = tm + (size_t)k * (R_ * P_ * R_);
        float* stCur = sState + (k & 1) * 2560;
        float* stNxt = sState + ((k & 1) ^ 1) * 2560;

        __syncthreads();  // state writes + last step's sM/sG reads done

        // Ck -> sCk as [q][a*8+b]
        for (int i = tid; i < CB_ * Q_ * CB_; i += THREADS) {
            int a  = i / (Q_ * CB_);
            int qb = i % (Q_ * CB_);
            int q = qb >> 3, b = qb & 7;
            sCk[q * 64 + a * 8 + b] = Ck[i];
        }
        __syncthreads();

        // M[p][ab] = sum_q x[p,q] * Ck[a,q,b]
        for (int e4 = tid; e4 < (P_ * 64) / 4; e4 += THREADS) {
            int p  = e4 >> 4;
            int c4 = e4 & 15;
            const float*  xp  = sx + p * Q_;
            const float4* ck4 = ((const float4*)sCk) + c4;
            float4 acc = make_float4(0.f, 0.f, 0.f, 0.f);
            #pragma unroll
            for (int q = 0; q < Q_; q++) {
                float  f  = xp[q];
                float4 cv = ck4[q * 16];
                acc.x += f * cv.x; acc.y += f * cv.y;
                acc.z += f * cv.z; acc.w += f * cv.w;
            }
            ((float4*)sM)[e4] = acc;
        }

        float ns[5];
        #pragma unroll
        for (int c = 0; c < 5; c++) ns[c] = 0.f;

        // 4 tiles over groups of 8 l-values; G tile [64 rows][8*32 cols]
        for (int lt = 0; lt < 4; lt++) {
            __syncthreads();  // sM ready (lt=0) / prev tile's G reads done

            const int   l   = lt * 8 + (colGrp >> 3);
            const int   r0  = (colGrp & 7) * 4;
            const float* AkL = Ak + (size_t)l * (P_ * R_) + r0;
            // this thread's 8 M-rows as packed f32x2 pairs
            const ulonglong2* mbase = ((const ulonglong2*)sM) + rowGrp * 2;

            uint64_t acc[16];
            #pragma unroll
            for (int i = 0; i < 16; i++) acc[i] = 0ull;

            // unroll-4 p loop, av prefetched one FULL body (4 p) ahead — no predication
            float4 av0 = *(const float4*)(AkL + 0 * R_);
            float4 av1 = *(const float4*)(AkL + 1 * R_);
            float4 av2 = *(const float4*)(AkL + 2 * R_);
            float4 av3 = *(const float4*)(AkL + 3 * R_);
            ulonglong2 ma = mbase[0];
            ulonglong2 mb = mbase[1];

            #pragma unroll 1
            for (int pb = 0; pb < P_ - 4; pb += 4) {
                float4 avn0 = *(const float4*)(AkL + (pb + 4) * R_);
                ulonglong2 ma1 = mbase[(pb + 1) * MSTRIDE];
                ulonglong2 mb1 = mbase[(pb + 1) * MSTRIDE + 1];
                FFMA2_BLOCK(acc, ma, mb, av0)

                float4 avn1 = *(const float4*)(AkL + (pb + 5) * R_);
                ulonglong2 ma2 = mbase[(pb + 2) * MSTRIDE];
                ulonglong2 mb2 = mbase[(pb + 2) * MSTRIDE + 1];
                FFMA2_BLOCK(acc, ma1, mb1, av1)

                float4 avn2 = *(const float4*)(AkL + (pb + 6) * R_);
                ulonglong2 ma3 = mbase[(pb + 3) * MSTRIDE];
                ulonglong2 mb3 = mbase[(pb + 3) * MSTRIDE + 1];
                FFMA2_BLOCK(acc, ma2, mb2, av2)

                float4 avn3 = *(const float4*)(AkL + (pb + 7) * R_);
                ma = mbase[(pb + 4) * MSTRIDE];
                mb = mbase[(pb + 4) * MSTRIDE + 1];
                FFMA2_BLOCK(acc, ma3, mb3, av3)

                av0 = avn0; av1 = avn1; av2 = avn2; av3 = avn3;
            }
            // tail: p = 192..195 (av0..av3 already loaded, ma/mb = row 192)
            {
                ulonglong2 ma1 = mbase[193 * MSTRIDE];
                ulonglong2 mb1 = mbase[193 * MSTRIDE + 1];
                FFMA2_BLOCK(acc, ma, mb, av0)
                ulonglong2 ma2 = mbase[194 * MSTRIDE];
                ulonglong2 mb2 = mbase[194 * MSTRIDE + 1];
                FFMA2_BLOCK(acc, ma1, mb1, av1)
                ulonglong2 ma3 = mbase[195 * MSTRIDE];
                ulonglong2 mb3 = mbase[195 * MSTRIDE + 1];
                FFMA2_BLOCK(acc, ma2, mb2, av2)
                FFMA2_BLOCK(acc, ma3, mb3, av3)
            }

            // write 8 rows x 4 cols to G
            float4* g4 = (float4*)sG;
            #pragma unroll
            for (int kk = 0; kk < 4; kk++) {
                float2 l0 = unpack2(acc[kk * 4 + 0]);
                float2 l1 = unpack2(acc[kk * 4 + 1]);
                float2 l2 = unpack2(acc[kk * 4 + 2]);
                float2 l3 = unpack2(acc[kk * 4 + 3]);
                g4[(rowGrp * 8 + kk * 2 + 0) * 64 + colGrp] =
                    make_float4(l0.x, l1.x, l2.x, l3.x);
                g4[(rowGrp * 8 + kk * 2 + 1) * 64 + colGrp] =
                    make_float4(l0.y, l1.y, l2.y, l3.y);
            }
            __syncthreads();  // G tile complete

            // ns[c] += sum_{a,lj} state[a, lt*8+lj, c] * G[a*8+bU, lj*32+rU]
            #pragma unroll
            for (int a = 0; a < CB_; a++) {
                #pragma unroll
                for (int lj = 0; lj < 8; lj++) {
                    float g = sG[(a * 8 + bU) * 256 + lj * 32 + rU];
                    const float* st = stCur + a * 320 + (lt * 8 + lj) * 10 + chU * 5;
                    #pragma unroll
                    for (int c = 0; c < 5; c++) ns[c] += st[c] * g;
                }
            }
        }

        #pragma unroll
        for (int c = 0; c < 5; c++) stNxt[bU * 320 + rU * 10 + chU * 5 + c] = ns[c];
    }

    // ---------- last carriage ----------
    __syncthreads();

    // z[p,a] = sum_q x[p,q] cl[a,q]  (into sM[p*8+a])
    for (int e = tid; e < P_ * CB_; e += THREADS) {
        int p = e >> 3, a = e & 7;
        const float* xp  = sx + p * Q_;
        const float* cla = cl + a * Q_;
        float acc = 0.f;
        #pragma unroll
        for (int q = 0; q < Q_; q++) acc += xp[q] * cla[q];
        sM[e] = acc;
    }
    if (tid < C_) sOut[tid] = 0.f;
    __syncthreads();

    // GN[a,l] = sum_p z[p,a] tl[l,p];  out[c] = sum_{a,l} state[a,l,c]*GN[a,l]
    if (tid < 256) {
        const int a = tid >> 5, l = tid & 31;
        const float* tlr = tl + l * P_;
        float gn = 0.f;
        for (int p = 0; p < P_; p++) gn += sM[p * 8 + a] * tlr[p];

        const float* st = sState + /*final buffer 0 (NMID even)*/ a * 320 + l * 10;
        #pragma unroll
        for (int c = 0; c < C_; c++) atomicAdd(&sOut[c], st[c] * gn);
    }
    __syncthreads();

    if (tid < C_) out[(size_t)s * C_ + tid] = sOut[tid];
}

extern "C" void kernel_launch(void* const* d_in, const int* in_sizes, int n_in,
                              void* d_out, int out_size)
{
    const float* x  = (const float*)d_in[0];
    const float* cf = (const float*)d_in[1];
    const float* cm = (const float*)d_in[2];
    const float* cl = (const float*)d_in[3];
    const float* tf = (const float*)d_in[4];
    const float* tm = (const float*)d_in[5];
    const float* tl = (const float*)d_in[6];
    float* out = (float*)d_out;

    size_t shbytes = SMEM_FLOATS * sizeof(float);
    cudaFuncSetAttribute(tctl_kernel, cudaFuncAttributeMaxDynamicSharedMemorySize,
                         (int)shbytes);
    tctl_kernel<<<S_, THREADS, shbytes>>>(x, cf, cm, cl, tf, tm, tl, out);
}